// round 8
// baseline (speedup 1.0000x reference)
#include <cuda_runtime.h>
#include <cuda_bf16.h>
#include <math.h>

#define S 512
#define B 64
#define H 512
#define D 512
#define G3 1536
#define NBLK 128

typedef unsigned u32;
typedef unsigned long long ull;
typedef __nv_bfloat16 bf16;

// ---------------- device-global scratch (allocation-free rule) ----------------
__device__ float g_gi0[(size_t)2 * S * B * G3];          // fp32 gi0 [dir][t][b][3H]
__device__ u32   g_xfrag[2][S][16384];                   // x in A-frag layout [plane][s]
__device__ u32   g_wfrag[2][2][393216];                  // Wih0 in B-frag layout [plane][dir]
__device__ float g_h0f[2][2][B * H];                     // [parity][dir]
__device__ float g_h1f[2][2][B * H];
// h planes in mma-frag layout: u32 idx = kblk*512 + mtile*128 + lane*4 + reg
__device__ u32   g_h0p[2][2][2][16384];                  // [parity][dir][plane]
__device__ u32   g_h1p[2][2][2][16384];
__device__ u32   g_slots[2][64];

// ---------------- helpers ----------------
__device__ __forceinline__ void split_bf(float v, bf16& hi, bf16& lo) {
    hi = __float2bfloat16(v);
    lo = __float2bfloat16(v - __bfloat162float(hi));
}
__device__ __forceinline__ u32 pack2(bf16 a, bf16 b) {
    return (u32)__bfloat16_as_ushort(a) | ((u32)__bfloat16_as_ushort(b) << 16);
}
__device__ __forceinline__ float sigm(float x) { return 1.0f / (1.0f + expf(-x)); }

// byte offset of h value (batch b, hidden k) inside a frag-layout plane
__device__ __forceinline__ int frag_byte(int b, int k) {
    int kblk = k >> 4, c = k & 15, mt = b >> 4, r = b & 15;
    int lane = (r & 7) * 4 + ((c & 7) >> 1);
    int reg  = (r >> 3) + 2 * (c >> 3);
    return ((kblk * 512 + mt * 128 + lane * 4 + reg) << 2) + ((c & 1) << 1);
}

__device__ __forceinline__ void mma16816(float* d, const u32* a, u32 b0, u32 b1) {
    asm volatile("mma.sync.aligned.m16n8k16.row.col.f32.bf16.bf16.f32 "
                 "{%0,%1,%2,%3},{%4,%5,%6,%7},{%8,%9},{%0,%1,%2,%3};"
                 : "+f"(d[0]), "+f"(d[1]), "+f"(d[2]), "+f"(d[3])
                 : "r"(a[0]), "r"(a[1]), "r"(a[2]), "r"(a[3]), "r"(b0), "r"(b1));
}
__device__ __forceinline__ void cp16(void* smem_dst, const void* gsrc) {
    u32 s = (u32)__cvta_generic_to_shared(smem_dst);
    asm volatile("cp.async.cg.shared.global [%0], [%1], 16;" :: "r"(s), "l"(gsrc));
}

// ---------------- conv_xw: input -> A-frags, Wih0 -> B-frags ----------------
// blocks [0,16384): x; [16384,17920): W
__global__ void conv_xw(const float* __restrict__ x,
                        const float* __restrict__ wf, const float* __restrict__ wb) {
    if (blockIdx.x < 16384) {
        size_t i = ((size_t)blockIdx.x * 256 + threadIdx.x) * 4;   // over B*S*D
        float4 v = *(const float4*)&x[i];
        int b  = (int)(i >> 18);
        int s  = (int)(i >> 9) & 511;
        int k0 = (int)i & 511;
        bf16 h0, l0, h1, l1, h2, l2, h3, l3;
        split_bf(v.x, h0, l0); split_bf(v.y, h1, l1);
        split_bf(v.z, h2, l2); split_bf(v.w, h3, l3);
        int kblk = k0 >> 4, c = k0 & 15, r = b & 15, mt = b >> 4;
        int lane = (r & 7) * 4 + ((c & 7) >> 1);
        int reg  = (r >> 3) + 2 * (c >> 3);
        int idx  = kblk * 512 + mt * 128 + lane * 4 + reg;
        g_xfrag[0][s][idx]     = pack2(h0, h1);
        g_xfrag[0][s][idx + 4] = pack2(h2, h3);
        g_xfrag[1][s][idx]     = pack2(l0, l1);
        g_xfrag[1][s][idx + 4] = pack2(l2, l3);
    } else {
        size_t j = ((size_t)(blockIdx.x - 16384) * 256 + threadIdx.x) * 4;  // over 2*G3*D
        int d = j >= (size_t)G3 * D;
        size_t off = d ? j - (size_t)G3 * D : j;
        const float* src = d ? wb : wf;
        float4 v = *(const float4*)&src[off];
        int n  = (int)(off >> 9);
        int k0 = (int)off & 511;
        bf16 h0, l0, h1, l1, h2, l2, h3, l3;
        split_bf(v.x, h0, l0); split_bf(v.y, h1, l1);
        split_bf(v.z, h2, l2); split_bf(v.w, h3, l3);
        int kblk = k0 >> 4;
        int lane = (n & 7) * 4 + ((k0 & 7) >> 1);
        int reg  = (k0 >> 3) & 1;
        int nblk = n >> 3;
        int base = ((kblk * 192 + nblk) * 32 + lane) * 2 + reg;
        g_wfrag[0][d][base]     = pack2(h0, h1);
        g_wfrag[0][d][base + 2] = pack2(h2, h3);
        g_wfrag[1][d][base]     = pack2(l0, l1);
        g_wfrag[1][d][base + 2] = pack2(l2, l3);
    }
}

// ---------------- init: hidden states (fp32 + frag planes) + slot reset ----------------
__global__ void init_h(const float* __restrict__ enc) {
    if (blockIdx.x == 0 && threadIdx.x < 128) {
        g_slots[threadIdx.x >> 6][threadIdx.x & 63] = 0;
    }
    int idx = blockIdx.x * blockDim.x + threadIdx.x;   // 131072
    int layer = idx >> 16;
    int rem = idx & 65535;
    int dir = rem >> 15;
    int rem2 = rem & 32767;
    int b = rem2 >> 9;
    int n = rem2 & 511;
    float v = enc[(layer * B + b) * (2 * H) + dir * H + n];
    bf16 hi, lo; split_bf(v, hi, lo);
    int off = frag_byte(b, n);
    if (layer == 0) {
        g_h0f[0][dir][b * H + n] = v;
        *(bf16*)((char*)g_h0p[0][dir][0] + off) = hi;
        *(bf16*)((char*)g_h0p[0][dir][1] + off) = lo;
    } else {
        g_h1f[0][dir][b * H + n] = v;
        *(bf16*)((char*)g_h1p[0][dir][0] + off) = hi;
        *(bf16*)((char*)g_h1p[0][dir][1] + off) = lo;
    }
}

// ---------------- gi0 = input @ Wih0^T + bih0: frag-direct, no smem ----------------
// grid (S, 24, 2), 256 thr = 8 warps (4 mtiles x 2 nhalves of 32). M=64, N=64, K=512.
__global__ void __launch_bounds__(256, 2)
gemm_gi0(const float* __restrict__ bf_, const float* __restrict__ bb_) {
    int s  = blockIdx.x;
    int nb = blockIdx.y;
    int d  = blockIdx.z;
    const float* bias = d ? bb_ : bf_;

    int tid = threadIdx.x;
    int w = tid >> 5, l = tid & 31;
    int mtile = w & 3, m0 = mtile * 16, nh = w >> 2;
    int moff  = mtile * 128 + l * 4;
    int nbase = nb * 8 + nh * 4;

    const u32* Xh = g_xfrag[0][s];
    const u32* Xl = g_xfrag[1][s];
    const u32* Wh = g_wfrag[0][d];
    const u32* Wl = g_wfrag[1][d];

    float acc[4][4];
#pragma unroll
    for (int nt = 0; nt < 4; nt++) { acc[nt][0] = acc[nt][1] = acc[nt][2] = acc[nt][3] = 0.f; }

    u32 a[3][2][4];
    u32 b[3][2][4][2];

    auto loadK = [&](int c, int slot) {
        uint4 v;
        v = __ldcg((const uint4*)(Xh + c * 512 + moff));
        a[slot][0][0] = v.x; a[slot][0][1] = v.y; a[slot][0][2] = v.z; a[slot][0][3] = v.w;
        v = __ldcg((const uint4*)(Xl + c * 512 + moff));
        a[slot][1][0] = v.x; a[slot][1][1] = v.y; a[slot][1][2] = v.z; a[slot][1][3] = v.w;
#pragma unroll
        for (int nt = 0; nt < 4; nt++) {
            int idx = ((c * 192 + nbase + nt) * 32 + l) * 2;
            uint2 u = __ldcg((const uint2*)(Wh + idx));
            b[slot][0][nt][0] = u.x; b[slot][0][nt][1] = u.y;
            uint2 w2 = __ldcg((const uint2*)(Wl + idx));
            b[slot][1][nt][0] = w2.x; b[slot][1][nt][1] = w2.y;
        }
    };

    loadK(0, 0);
    loadK(1, 1);
#pragma unroll
    for (int c = 0; c < 32; c++) {
        int slot = c % 3;
        if (c < 30) loadK(c + 2, (c + 2) % 3);
#pragma unroll
        for (int nt = 0; nt < 4; nt++) {
            mma16816(acc[nt], a[slot][0], b[slot][0][nt][0], b[slot][0][nt][1]);
            mma16816(acc[nt], a[slot][1], b[slot][0][nt][0], b[slot][0][nt][1]);
            mma16816(acc[nt], a[slot][0], b[slot][1][nt][0], b[slot][1][nt][1]);
        }
    }

#pragma unroll
    for (int nt = 0; nt < 4; nt++) {
        int col = nb * 64 + nh * 32 + nt * 8 + 2 * (l & 3);
        float2 bi = *(const float2*)&bias[col];
        int b0 = m0 + (l >> 2);
        float2 v0 = make_float2(acc[nt][0] + bi.x, acc[nt][1] + bi.y);
        float2 v1 = make_float2(acc[nt][2] + bi.x, acc[nt][3] + bi.y);
        *(float2*)&g_gi0[(((size_t)d * S + s) * B + b0) * G3 + col] = v0;
        *(float2*)&g_gi0[(((size_t)d * S + s) * B + b0 + 8) * G3 + col] = v1;
    }
}

// ---------------- per-dir grid barrier: slot array, no atomic serialization ----------------
__device__ __forceinline__ void grid_bar(int dir, int slot_id, unsigned target) {
    __syncthreads();
    if (threadIdx.x < 32) {
        if (threadIdx.x == 0) {
            asm volatile("st.release.gpu.u32 [%0], %1;"
                         :: "l"(&g_slots[dir][slot_id]), "r"(target) : "memory");
        }
        const u32* s0 = &g_slots[dir][threadIdx.x];
        const u32* s1 = &g_slots[dir][threadIdx.x + 32];
        bool wait = true;
        do {
            u32 va, vb;
            asm volatile("ld.acquire.gpu.u32 %0, [%1];" : "=r"(va) : "l"(s0) : "memory");
            asm volatile("ld.acquire.gpu.u32 %0, [%1];" : "=r"(vb) : "l"(s1) : "memory");
            wait = (va < target) || (vb < target);
        } while (__ballot_sync(0xffffffffu, wait));
    }
    __syncthreads();
}

// ---------------- persistent recurrence kernel ----------------
// grid 128 (2 dir x 64 hgroups of 8), 512 thr = 16 warps (mtile x4, ksub x4).
// smem: WS 152064 | GA/GB/GC 19968 | GI0S 6144 = 178176 B
__global__ void __launch_bounds__(512, 1)
gru_persist(const float* __restrict__ Wih_f, const float* __restrict__ Wih_b,
            const float* __restrict__ Whh_f, const float* __restrict__ Whh_b,
            const float* __restrict__ bih_f, const float* __restrict__ bih_b,
            const float* __restrict__ bhh_f, const float* __restrict__ bhh_b,
            float* __restrict__ out) {
    extern __shared__ char smem[];
    u32*  WS   = (u32*)smem;                     // [(mat*2+plane)*24 + n][264]
    float* GA  = (float*)(smem + 152064);        // [64][26]
    float* GB  = (float*)(smem + 158720);
    float* GC  = (float*)(smem + 165376);
    float* GI0S = (float*)(smem + 172032);       // [64][24]

    const int tid = threadIdx.x;
    const int bid = blockIdx.x;
    const int dir = bid >> 6;
    const int hb  = (bid & 63) * 8;
    const int w = tid >> 5, l = tid & 31;
    const int mtile = w & 3, m0 = mtile * 16, ksub = w >> 2;

    const float* Wih = dir ? Wih_b : Wih_f;
    const float* Whh = dir ? Whh_b : Whh_f;
    const float* bih = dir ? bih_b : bih_f;
    const float* bhh = dir ? bhh_b : bhh_f;
    const float* bhh0 = bhh;
    const float* bi1 = bih + G3;
    const float* bh1 = bhh + G3;

    // ---- one-time weight staging: bf16 hi/lo, (k,k+8)-interleaved u32 pairs ----
    {
        const float* Wmat[3] = { Whh, Wih + (size_t)G3 * D, Whh + (size_t)G3 * H };
#pragma unroll 4
        for (int i = 0; i < 36; i++) {
            int item = tid + 512 * i;            // < 18432
            int m3 = item / 6144;
            int rem = item - m3 * 6144;
            int n = rem >> 8;
            int k2 = rem & 255;
            int grow = (n >> 3) * H + hb + (n & 7);
            float2 v = *(const float2*)(Wmat[m3] + (size_t)grow * 512 + 2 * k2);
            bf16 h0, l0, h1, l1;
            split_bf(v.x, h0, l0); split_bf(v.y, h1, l1);
            int j = k2 & 7;
            int col = ((k2 >> 3) << 3) + ((j & 3) << 1) + (j >> 2);
            WS[((m3 * 2 + 0) * 24 + n) * 264 + col] = pack2(h0, h1);
            WS[((m3 * 2 + 1) * 24 + n) * 264 + col] = pack2(l0, l1);
        }
    }

    const int rowoff = (l >> 2) * 264 + 2 * (l & 3) + ksub * 8;
    const int fbase  = mtile * 128 + l * 4;

    for (int p = 0; p <= S; p++) {
        const u32* Apl[4] = { g_h0p[p & 1][dir][0], g_h0p[p & 1][dir][1],
                              g_h1p[(p + 1) & 1][dir][0], g_h1p[(p + 1) & 1][dir][1] };
        const float* Xf = g_h0f[p & 1][dir];
        const float* Hf = g_h1f[(p + 1) & 1][dir];

        // gi0 prefetch (used in L0 epilogue)
        if (p < S) {
            int tt0 = dir ? (S - 1 - p) : p;
            const float* gi = &g_gi0[((size_t)dir * S + tt0) * B * G3];
            if (tid < 384) {
                int mm = tid / 6, r = tid % 6;
                int gate = r >> 1, half = r & 1;
                cp16(&GI0S[mm * 24 + gate * 8 + half * 4],
                     gi + mm * G3 + gate * H + hb + half * 4);
            }
            asm volatile("cp.async.commit_group;");
        }

        float acc[3][3][4];
#pragma unroll
        for (int m3 = 0; m3 < 3; m3++)
#pragma unroll
            for (int nt = 0; nt < 3; nt++)
                acc[m3][nt][0] = acc[m3][nt][1] = acc[m3][nt][2] = acc[m3][nt][3] = 0.f;

        u32 f[3][4][4];
        auto loadf = [&](int c, int slot) {
            int idx = (c * 4 + ksub) * 512 + fbase;
#pragma unroll
            for (int pl = 0; pl < 4; pl++) {
                uint4 v = __ldcg((const uint4*)(Apl[pl] + idx));
                f[slot][pl][0] = v.x; f[slot][pl][1] = v.y;
                f[slot][pl][2] = v.z; f[slot][pl][3] = v.w;
            }
        };
        loadf(0, 0);
        loadf(1, 1);

#pragma unroll
        for (int c = 0; c < 8; c++) {
            int slot = c % 3;
            if (c < 6) loadf(c + 2, (c + 2) % 3);
            const int cb = rowoff + c * 32;
#pragma unroll
            for (int m3 = 0; m3 < 3; m3++) {
                const u32* Ahi = (m3 == 2) ? f[slot][2] : f[slot][0];
                const u32* Alo = (m3 == 2) ? f[slot][3] : f[slot][1];
                const u32* WH = WS + (m3 * 2) * 24 * 264 + cb;
                const u32* WL = WH + 24 * 264;
#pragma unroll
                for (int nt = 0; nt < 3; nt++) {
                    ull wh64 = *(const ull*)(WH + nt * 8 * 264);
                    ull wl64 = *(const ull*)(WL + nt * 8 * 264);
                    u32 bh0 = (u32)wh64, bh1 = (u32)(wh64 >> 32);
                    u32 bl0 = (u32)wl64, bl1 = (u32)(wl64 >> 32);
                    mma16816(acc[m3][nt], Ahi, bh0, bh1);
                    mma16816(acc[m3][nt], Alo, bh0, bh1);
                    mma16816(acc[m3][nt], Ahi, bl0, bl1);
                }
            }
        }

        // ---- K-split reduction into GA/GB/GC ----
        __syncthreads();
#pragma unroll
        for (int r = 0; r < 4; r++) {
            if (ksub == r) {
#pragma unroll
                for (int m3 = 0; m3 < 3; m3++) {
                    float* G = (m3 == 0) ? GA : (m3 == 1) ? GB : GC;
#pragma unroll
                    for (int nt = 0; nt < 3; nt++) {
                        int col = nt * 8 + 2 * (l & 3);
                        int r0 = m0 + (l >> 2);
                        float2* p0 = (float2*)&G[r0 * 26 + col];
                        float2* p1 = (float2*)&G[(r0 + 8) * 26 + col];
                        float2 v0 = make_float2(acc[m3][nt][0], acc[m3][nt][1]);
                        float2 v1 = make_float2(acc[m3][nt][2], acc[m3][nt][3]);
                        if (r) {
                            float2 o;
                            o = *p0; v0.x += o.x; v0.y += o.y;
                            o = *p1; v1.x += o.x; v1.y += o.y;
                        }
                        *p0 = v0; *p1 = v1;
                    }
                }
            }
            __syncthreads();
        }
        asm volatile("cp.async.wait_group 0;");

        // ---- L0 epilogue: t = p ----
        if (p < S) {
            float* Xnf = g_h0f[(p + 1) & 1][dir];
            char* Xnh = (char*)g_h0p[(p + 1) & 1][dir][0];
            char* Xnl = (char*)g_h0p[(p + 1) & 1][dir][1];
            int mm = tid & 63;
            int j  = tid >> 6;
            int row = hb + j;
            float hr = GA[mm * 26 + j]      + bhh0[row];
            float hz = GA[mm * 26 + 8 + j]  + bhh0[H + row];
            float hn = GA[mm * 26 + 16 + j] + bhh0[2 * H + row];
            float rr = sigm(GI0S[mm * 24 + j] + hr);
            float zz = sigm(GI0S[mm * 24 + 8 + j] + hz);
            float nn = tanhf(GI0S[mm * 24 + 16 + j] + rr * hn);
            float hp = __ldcg(&Xf[mm * H + row]);
            float hnew = (1.0f - zz) * nn + zz * hp;
            Xnf[mm * H + row] = hnew;
            bf16 hi, lo; split_bf(hnew, hi, lo);
            int off = frag_byte(mm, row);
            *(bf16*)(Xnh + off) = hi;
            *(bf16*)(Xnl + off) = lo;
        }

        // ---- L1 epilogue: t = p-1 ----
        if (p >= 1) {
            int t1 = p - 1;
            int tt = dir ? (S - 1 - t1) : t1;
            float* Hnf = g_h1f[p & 1][dir];
            char* Hnh = (char*)g_h1p[p & 1][dir][0];
            char* Hnl = (char*)g_h1p[p & 1][dir][1];
            int mm = tid & 63;
            int j  = tid >> 6;
            int row = hb + j;
            float ir  = GB[mm * 26 + j]      + bi1[row];
            float iz  = GB[mm * 26 + 8 + j]  + bi1[H + row];
            float inn = GB[mm * 26 + 16 + j] + bi1[2 * H + row];
            float hr  = GC[mm * 26 + j]      + bh1[row];
            float hz  = GC[mm * 26 + 8 + j]  + bh1[H + row];
            float hn  = GC[mm * 26 + 16 + j] + bh1[2 * H + row];
            float rr = sigm(ir + hr);
            float zz = sigm(iz + hz);
            float nn = tanhf(inn + rr * hn);
            float hp = __ldcg(&Hf[mm * H + row]);
            float hnew = (1.0f - zz) * nn + zz * hp;
            Hnf[mm * H + row] = hnew;
            bf16 hi, lo; split_bf(hnew, hi, lo);
            int off = frag_byte(mm, row);
            *(bf16*)(Hnh + off) = hi;
            *(bf16*)(Hnl + off) = lo;
            out[(size_t)mm * (S * 2 * H) + (size_t)tt * (2 * H) + dir * H + row] = hnew;
        }

        grid_bar(dir, bid & 63, (unsigned)(p + 1));
    }

    // ---- final hidden state copy (own dir; parity 0) ----
#pragma unroll
    for (int it = 0; it < 2; it++) {
        int local = (bid & 63) * 1024 + it * 512 + tid;   // < 65536 per dir
        int lyr = local >> 15;
        int rem = local & 32767;
        int b = rem >> 9;
        int n = rem & 511;
        float v = lyr ? __ldcg(&g_h1f[0][dir][b * H + n]) : __ldcg(&g_h0f[0][dir][b * H + n]);
        out[(size_t)B * S * 2 * H + ((size_t)lyr * B + b) * (2 * H) + dir * H + n] = v;
    }
}

// ---------------- launch ----------------
extern "C" void kernel_launch(void* const* d_in, const int* in_sizes, int n_in,
                              void* d_out, int out_size) {
    const float* input  = (const float*)d_in[0];
    const float* enc    = (const float*)d_in[1];
    const float* Wih_f  = (const float*)d_in[2];
    const float* Whh_f  = (const float*)d_in[3];
    const float* bih_f  = (const float*)d_in[4];
    const float* bhh_f  = (const float*)d_in[5];
    const float* Wih_b  = (const float*)d_in[6];
    const float* Whh_b  = (const float*)d_in[7];
    const float* bih_b  = (const float*)d_in[8];
    const float* bhh_b  = (const float*)d_in[9];
    float* out = (float*)d_out;

    const int SMEM_P = 178176;
    static int configured = 0;
    if (!configured) {
        cudaFuncSetAttribute(gru_persist, cudaFuncAttributeMaxDynamicSharedMemorySize, SMEM_P);
        configured = 1;
    }

    conv_xw<<<17920, 256>>>(input, Wih_f, Wih_b);
    init_h<<<512, 256>>>(enc);
    gemm_gi0<<<dim3(S, 24, 2), 256>>>(bih_f, bih_b);
    gru_persist<<<NBLK, 512, SMEM_P>>>(Wih_f, Wih_b, Whh_f, Whh_b,
                                       bih_f, bih_b, bhh_f, bhh_b, out);
}

// round 9
// speedup vs baseline: 1.9846x; 1.9846x over previous
#include <cuda_runtime.h>
#include <cuda_bf16.h>
#include <math.h>

#define S 512
#define B 64
#define H 512
#define D 512
#define G3 1536
#define NBLK 128

typedef unsigned u32;
typedef unsigned long long ull;
typedef __nv_bfloat16 bf16;

// ---------------- device-global scratch (allocation-free rule) ----------------
__device__ float g_gi0[(size_t)2 * S * B * G3];          // fp32 gi0 [dir][t][b][3H]
__device__ u32   g_xfrag[2][S][16384];                   // x in A-frag layout [plane][s]
__device__ u32   g_wfrag[2][2][393216];                  // Wih0 in B-frag layout [plane][dir]
__device__ float g_h0f[2][2][B * H];                     // [parity][dir]
__device__ float g_h1f[2][2][B * H];
// h planes in mma-frag layout: u32 idx = kblk*512 + mtile*128 + lane*4 + reg
__device__ u32   g_h0p[2][2][2][16384];                  // [parity][dir][plane]
__device__ u32   g_h1p[2][2][2][16384];
__device__ unsigned g_arrive2[2];
__device__ unsigned g_release2[2];

// ---------------- helpers ----------------
__device__ __forceinline__ void split_bf(float v, bf16& hi, bf16& lo) {
    hi = __float2bfloat16(v);
    lo = __float2bfloat16(v - __bfloat162float(hi));
}
__device__ __forceinline__ u32 pack2(bf16 a, bf16 b) {
    return (u32)__bfloat16_as_ushort(a) | ((u32)__bfloat16_as_ushort(b) << 16);
}
__device__ __forceinline__ float sigm(float x) { return 1.0f / (1.0f + expf(-x)); }

// byte offset of h value (batch b, hidden k) inside a frag-layout plane
__device__ __forceinline__ int frag_byte(int b, int k) {
    int kblk = k >> 4, c = k & 15, mt = b >> 4, r = b & 15;
    int lane = (r & 7) * 4 + ((c & 7) >> 1);
    int reg  = (r >> 3) + 2 * (c >> 3);
    return ((kblk * 512 + mt * 128 + lane * 4 + reg) << 2) + ((c & 1) << 1);
}

__device__ __forceinline__ void mma16816(float* d, const u32* a, u32 b0, u32 b1) {
    asm volatile("mma.sync.aligned.m16n8k16.row.col.f32.bf16.bf16.f32 "
                 "{%0,%1,%2,%3},{%4,%5,%6,%7},{%8,%9},{%0,%1,%2,%3};"
                 : "+f"(d[0]), "+f"(d[1]), "+f"(d[2]), "+f"(d[3])
                 : "r"(a[0]), "r"(a[1]), "r"(a[2]), "r"(a[3]), "r"(b0), "r"(b1));
}
__device__ __forceinline__ void cp16(void* smem_dst, const void* gsrc) {
    u32 s = (u32)__cvta_generic_to_shared(smem_dst);
    asm volatile("cp.async.cg.shared.global [%0], [%1], 16;" :: "r"(s), "l"(gsrc));
}

// ---------------- conv_xw: input -> A-frags, Wih0 -> B-frags ----------------
// blocks [0,16384): x; [16384,17920): W
__global__ void conv_xw(const float* __restrict__ x,
                        const float* __restrict__ wf, const float* __restrict__ wb) {
    if (blockIdx.x < 16384) {
        size_t i = ((size_t)blockIdx.x * 256 + threadIdx.x) * 4;   // over B*S*D
        float4 v = *(const float4*)&x[i];
        int b  = (int)(i >> 18);
        int s  = (int)(i >> 9) & 511;
        int k0 = (int)i & 511;
        bf16 h0, l0, h1, l1, h2, l2, h3, l3;
        split_bf(v.x, h0, l0); split_bf(v.y, h1, l1);
        split_bf(v.z, h2, l2); split_bf(v.w, h3, l3);
        int kblk = k0 >> 4, c = k0 & 15, r = b & 15, mt = b >> 4;
        int lane = (r & 7) * 4 + ((c & 7) >> 1);
        int reg  = (r >> 3) + 2 * (c >> 3);
        int idx  = kblk * 512 + mt * 128 + lane * 4 + reg;
        g_xfrag[0][s][idx]     = pack2(h0, h1);
        g_xfrag[0][s][idx + 4] = pack2(h2, h3);
        g_xfrag[1][s][idx]     = pack2(l0, l1);
        g_xfrag[1][s][idx + 4] = pack2(l2, l3);
    } else {
        size_t j = ((size_t)(blockIdx.x - 16384) * 256 + threadIdx.x) * 4;  // over 2*G3*D
        int d = j >= (size_t)G3 * D;
        size_t off = d ? j - (size_t)G3 * D : j;
        const float* src = d ? wb : wf;
        float4 v = *(const float4*)&src[off];
        int n  = (int)(off >> 9);
        int k0 = (int)off & 511;
        bf16 h0, l0, h1, l1, h2, l2, h3, l3;
        split_bf(v.x, h0, l0); split_bf(v.y, h1, l1);
        split_bf(v.z, h2, l2); split_bf(v.w, h3, l3);
        int kblk = k0 >> 4;
        int lane = (n & 7) * 4 + ((k0 & 7) >> 1);
        int reg  = (k0 >> 3) & 1;
        int nblk = n >> 3;
        int base = ((kblk * 192 + nblk) * 32 + lane) * 2 + reg;
        g_wfrag[0][d][base]     = pack2(h0, h1);
        g_wfrag[0][d][base + 2] = pack2(h2, h3);
        g_wfrag[1][d][base]     = pack2(l0, l1);
        g_wfrag[1][d][base + 2] = pack2(l2, l3);
    }
}

// ---------------- init: hidden states (fp32 + frag planes) + barrier reset ----------------
__global__ void init_h(const float* __restrict__ enc) {
    if (blockIdx.x == 0 && threadIdx.x < 2) {
        g_arrive2[threadIdx.x] = 0;
        g_release2[threadIdx.x] = 0;
    }
    int idx = blockIdx.x * blockDim.x + threadIdx.x;   // 131072
    int layer = idx >> 16;
    int rem = idx & 65535;
    int dir = rem >> 15;
    int rem2 = rem & 32767;
    int b = rem2 >> 9;
    int n = rem2 & 511;
    float v = enc[(layer * B + b) * (2 * H) + dir * H + n];
    bf16 hi, lo; split_bf(v, hi, lo);
    int off = frag_byte(b, n);
    if (layer == 0) {
        g_h0f[0][dir][b * H + n] = v;
        *(bf16*)((char*)g_h0p[0][dir][0] + off) = hi;
        *(bf16*)((char*)g_h0p[0][dir][1] + off) = lo;
    } else {
        g_h1f[0][dir][b * H + n] = v;
        *(bf16*)((char*)g_h1p[0][dir][0] + off) = hi;
        *(bf16*)((char*)g_h1p[0][dir][1] + off) = lo;
    }
}

// ---------------- gi0 = input @ Wih0^T + bih0: frag-direct, no smem ----------------
// grid (S, 24, 2), 256 thr = 8 warps (4 mtiles x 2 nhalves of 32). M=64, N=64, K=512.
__global__ void __launch_bounds__(256, 2)
gemm_gi0(const float* __restrict__ bf_, const float* __restrict__ bb_) {
    int s  = blockIdx.x;
    int nb = blockIdx.y;
    int d  = blockIdx.z;
    const float* bias = d ? bb_ : bf_;

    int tid = threadIdx.x;
    int w = tid >> 5, l = tid & 31;
    int mtile = w & 3, m0 = mtile * 16, nh = w >> 2;
    int moff  = mtile * 128 + l * 4;
    int nbase = nb * 8 + nh * 4;

    const u32* Xh = g_xfrag[0][s];
    const u32* Xl = g_xfrag[1][s];
    const u32* Wh = g_wfrag[0][d];
    const u32* Wl = g_wfrag[1][d];

    float acc[4][4];
#pragma unroll
    for (int nt = 0; nt < 4; nt++) { acc[nt][0] = acc[nt][1] = acc[nt][2] = acc[nt][3] = 0.f; }

    u32 a[3][2][4];
    u32 b[3][2][4][2];

    auto loadK = [&](int c, int slot) {
        uint4 v;
        v = __ldcg((const uint4*)(Xh + c * 512 + moff));
        a[slot][0][0] = v.x; a[slot][0][1] = v.y; a[slot][0][2] = v.z; a[slot][0][3] = v.w;
        v = __ldcg((const uint4*)(Xl + c * 512 + moff));
        a[slot][1][0] = v.x; a[slot][1][1] = v.y; a[slot][1][2] = v.z; a[slot][1][3] = v.w;
#pragma unroll
        for (int nt = 0; nt < 4; nt++) {
            int idx = ((c * 192 + nbase + nt) * 32 + l) * 2;
            uint2 u = __ldcg((const uint2*)(Wh + idx));
            b[slot][0][nt][0] = u.x; b[slot][0][nt][1] = u.y;
            uint2 w2 = __ldcg((const uint2*)(Wl + idx));
            b[slot][1][nt][0] = w2.x; b[slot][1][nt][1] = w2.y;
        }
    };

    loadK(0, 0);
    loadK(1, 1);
#pragma unroll
    for (int c = 0; c < 32; c++) {
        int slot = c % 3;
        if (c < 30) loadK(c + 2, (c + 2) % 3);
#pragma unroll
        for (int nt = 0; nt < 4; nt++) {
            mma16816(acc[nt], a[slot][0], b[slot][0][nt][0], b[slot][0][nt][1]);
            mma16816(acc[nt], a[slot][1], b[slot][0][nt][0], b[slot][0][nt][1]);
            mma16816(acc[nt], a[slot][0], b[slot][1][nt][0], b[slot][1][nt][1]);
        }
    }

#pragma unroll
    for (int nt = 0; nt < 4; nt++) {
        int col = nb * 64 + nh * 32 + nt * 8 + 2 * (l & 3);
        float2 bi = *(const float2*)&bias[col];
        int b0 = m0 + (l >> 2);
        float2 v0 = make_float2(acc[nt][0] + bi.x, acc[nt][1] + bi.y);
        float2 v1 = make_float2(acc[nt][2] + bi.x, acc[nt][3] + bi.y);
        *(float2*)&g_gi0[(((size_t)d * S + s) * B + b0) * G3 + col] = v0;
        *(float2*)&g_gi0[(((size_t)d * S + s) * B + b0 + 8) * G3 + col] = v1;
    }
}

// ---------------- per-dir grid barrier (R7 proven design) ----------------
__device__ __forceinline__ void grid_bar(int dir, unsigned target) {
    __syncthreads();
    if (threadIdx.x == 0) {
        __threadfence();
        unsigned v = atomicAdd(&g_arrive2[dir], 1u) + 1u;
        if (v == target * 64u) {
            asm volatile("st.release.gpu.u32 [%0], %1;" :: "l"(&g_release2[dir]), "r"(target) : "memory");
        } else {
            unsigned r;
            do {
                asm volatile("ld.acquire.gpu.u32 %0, [%1];" : "=r"(r) : "l"(&g_release2[dir]) : "memory");
            } while (r < target);
        }
    }
    __syncthreads();
}

// ---------------- persistent recurrence kernel ----------------
// grid 128 (2 dir x 64 hgroups of 8), 512 thr = 16 warps (mtile x4, ksub x4).
// smem: WS 152064 | GA/GB/GC 19968 | GI0S 6144 = 178176 B
__global__ void __launch_bounds__(512, 1)
gru_persist(const float* __restrict__ Wih_f, const float* __restrict__ Wih_b,
            const float* __restrict__ Whh_f, const float* __restrict__ Whh_b,
            const float* __restrict__ bih_f, const float* __restrict__ bih_b,
            const float* __restrict__ bhh_f, const float* __restrict__ bhh_b,
            float* __restrict__ out) {
    extern __shared__ char smem[];
    u32*  WS   = (u32*)smem;                     // [(mat*2+plane)*24 + n][264]
    float* GA  = (float*)(smem + 152064);        // [64][26]
    float* GB  = (float*)(smem + 158720);
    float* GC  = (float*)(smem + 165376);
    float* GI0S = (float*)(smem + 172032);       // [64][24]

    const int tid = threadIdx.x;
    const int bid = blockIdx.x;
    const int dir = bid >> 6;
    const int hb  = (bid & 63) * 8;
    const int w = tid >> 5, l = tid & 31;
    const int mtile = w & 3, m0 = mtile * 16, ksub = w >> 2;

    const float* Wih = dir ? Wih_b : Wih_f;
    const float* Whh = dir ? Whh_b : Whh_f;
    const float* bih = dir ? bih_b : bih_f;
    const float* bhh = dir ? bhh_b : bhh_f;
    const float* bhh0 = bhh;
    const float* bi1 = bih + G3;
    const float* bh1 = bhh + G3;

    // ---- one-time weight staging: bf16 hi/lo, (k,k+8)-interleaved u32 pairs ----
    {
        const float* Wmat[3] = { Whh, Wih + (size_t)G3 * D, Whh + (size_t)G3 * H };
#pragma unroll 4
        for (int i = 0; i < 36; i++) {
            int item = tid + 512 * i;            // < 18432
            int m3 = item / 6144;
            int rem = item - m3 * 6144;
            int n = rem >> 8;
            int k2 = rem & 255;
            int grow = (n >> 3) * H + hb + (n & 7);
            float2 v = *(const float2*)(Wmat[m3] + (size_t)grow * 512 + 2 * k2);
            bf16 h0, l0, h1, l1;
            split_bf(v.x, h0, l0); split_bf(v.y, h1, l1);
            int j = k2 & 7;
            int col = ((k2 >> 3) << 3) + ((j & 3) << 1) + (j >> 2);
            WS[((m3 * 2 + 0) * 24 + n) * 264 + col] = pack2(h0, h1);
            WS[((m3 * 2 + 1) * 24 + n) * 264 + col] = pack2(l0, l1);
        }
    }

    const int rowoff = (l >> 2) * 264 + 2 * (l & 3) + ksub * 8;
    const int fbase  = mtile * 128 + l * 4;

    for (int p = 0; p <= S; p++) {
        const u32* Apl[4] = { g_h0p[p & 1][dir][0], g_h0p[p & 1][dir][1],
                              g_h1p[(p + 1) & 1][dir][0], g_h1p[(p + 1) & 1][dir][1] };
        const float* Xf = g_h0f[p & 1][dir];
        const float* Hf = g_h1f[(p + 1) & 1][dir];

        // gi0 prefetch (used in L0 epilogue)
        if (p < S) {
            int tt0 = dir ? (S - 1 - p) : p;
            const float* gi = &g_gi0[((size_t)dir * S + tt0) * B * G3];
            if (tid < 384) {
                int mm = tid / 6, r = tid % 6;
                int gate = r >> 1, half = r & 1;
                cp16(&GI0S[mm * 24 + gate * 8 + half * 4],
                     gi + mm * G3 + gate * H + hb + half * 4);
            }
            asm volatile("cp.async.commit_group;");
        }

        float acc[3][3][4];
#pragma unroll
        for (int m3 = 0; m3 < 3; m3++)
#pragma unroll
            for (int nt = 0; nt < 3; nt++)
                acc[m3][nt][0] = acc[m3][nt][1] = acc[m3][nt][2] = acc[m3][nt][3] = 0.f;

        u32 f[3][4][4];
        auto loadf = [&](int c, int slot) {
            int idx = (c * 4 + ksub) * 512 + fbase;
#pragma unroll
            for (int pl = 0; pl < 4; pl++) {
                uint4 v = __ldcg((const uint4*)(Apl[pl] + idx));
                f[slot][pl][0] = v.x; f[slot][pl][1] = v.y;
                f[slot][pl][2] = v.z; f[slot][pl][3] = v.w;
            }
        };
        loadf(0, 0);
        loadf(1, 1);

#pragma unroll
        for (int c = 0; c < 8; c++) {
            int slot = c % 3;
            if (c < 6) loadf(c + 2, (c + 2) % 3);
            const int cb = rowoff + c * 32;
#pragma unroll
            for (int m3 = 0; m3 < 3; m3++) {
                const u32* Ahi = (m3 == 2) ? f[slot][2] : f[slot][0];
                const u32* Alo = (m3 == 2) ? f[slot][3] : f[slot][1];
                const u32* WH = WS + (m3 * 2) * 24 * 264 + cb;
                const u32* WL = WH + 24 * 264;
#pragma unroll
                for (int nt = 0; nt < 3; nt++) {
                    ull wh64 = *(const ull*)(WH + nt * 8 * 264);
                    ull wl64 = *(const ull*)(WL + nt * 8 * 264);
                    u32 bh0 = (u32)wh64, bh1 = (u32)(wh64 >> 32);
                    u32 bl0 = (u32)wl64, bl1 = (u32)(wl64 >> 32);
                    mma16816(acc[m3][nt], Ahi, bh0, bh1);
                    mma16816(acc[m3][nt], Alo, bh0, bh1);
                    mma16816(acc[m3][nt], Ahi, bl0, bl1);
                }
            }
        }

        // ---- K-split reduction into GA/GB/GC ----
        __syncthreads();
#pragma unroll
        for (int r = 0; r < 4; r++) {
            if (ksub == r) {
#pragma unroll
                for (int m3 = 0; m3 < 3; m3++) {
                    float* G = (m3 == 0) ? GA : (m3 == 1) ? GB : GC;
#pragma unroll
                    for (int nt = 0; nt < 3; nt++) {
                        int col = nt * 8 + 2 * (l & 3);
                        int r0 = m0 + (l >> 2);
                        float2* p0 = (float2*)&G[r0 * 26 + col];
                        float2* p1 = (float2*)&G[(r0 + 8) * 26 + col];
                        float2 v0 = make_float2(acc[m3][nt][0], acc[m3][nt][1]);
                        float2 v1 = make_float2(acc[m3][nt][2], acc[m3][nt][3]);
                        if (r) {
                            float2 o;
                            o = *p0; v0.x += o.x; v0.y += o.y;
                            o = *p1; v1.x += o.x; v1.y += o.y;
                        }
                        *p0 = v0; *p1 = v1;
                    }
                }
            }
            __syncthreads();
        }
        asm volatile("cp.async.wait_group 0;");

        // ---- L0 epilogue: t = p ----
        if (p < S) {
            float* Xnf = g_h0f[(p + 1) & 1][dir];
            char* Xnh = (char*)g_h0p[(p + 1) & 1][dir][0];
            char* Xnl = (char*)g_h0p[(p + 1) & 1][dir][1];
            int mm = tid & 63;
            int j  = tid >> 6;
            int row = hb + j;
            float hr = GA[mm * 26 + j]      + bhh0[row];
            float hz = GA[mm * 26 + 8 + j]  + bhh0[H + row];
            float hn = GA[mm * 26 + 16 + j] + bhh0[2 * H + row];
            float rr = sigm(GI0S[mm * 24 + j] + hr);
            float zz = sigm(GI0S[mm * 24 + 8 + j] + hz);
            float nn = tanhf(GI0S[mm * 24 + 16 + j] + rr * hn);
            float hp = __ldcg(&Xf[mm * H + row]);
            float hnew = (1.0f - zz) * nn + zz * hp;
            Xnf[mm * H + row] = hnew;
            bf16 hi, lo; split_bf(hnew, hi, lo);
            int off = frag_byte(mm, row);
            *(bf16*)(Xnh + off) = hi;
            *(bf16*)(Xnl + off) = lo;
        }

        // ---- L1 epilogue: t = p-1 ----
        if (p >= 1) {
            int t1 = p - 1;
            int tt = dir ? (S - 1 - t1) : t1;
            float* Hnf = g_h1f[p & 1][dir];
            char* Hnh = (char*)g_h1p[p & 1][dir][0];
            char* Hnl = (char*)g_h1p[p & 1][dir][1];
            int mm = tid & 63;
            int j  = tid >> 6;
            int row = hb + j;
            float ir  = GB[mm * 26 + j]      + bi1[row];
            float iz  = GB[mm * 26 + 8 + j]  + bi1[H + row];
            float inn = GB[mm * 26 + 16 + j] + bi1[2 * H + row];
            float hr  = GC[mm * 26 + j]      + bh1[row];
            float hz  = GC[mm * 26 + 8 + j]  + bh1[H + row];
            float hn  = GC[mm * 26 + 16 + j] + bh1[2 * H + row];
            float rr = sigm(ir + hr);
            float zz = sigm(iz + hz);
            float nn = tanhf(inn + rr * hn);
            float hp = __ldcg(&Hf[mm * H + row]);
            float hnew = (1.0f - zz) * nn + zz * hp;
            Hnf[mm * H + row] = hnew;
            bf16 hi, lo; split_bf(hnew, hi, lo);
            int off = frag_byte(mm, row);
            *(bf16*)(Hnh + off) = hi;
            *(bf16*)(Hnl + off) = lo;
            out[(size_t)mm * (S * 2 * H) + (size_t)tt * (2 * H) + dir * H + row] = hnew;
        }

        grid_bar(dir, (unsigned)(p + 1));
    }

    // ---- final hidden state copy (own dir; parity 0) ----
#pragma unroll
    for (int it = 0; it < 2; it++) {
        int local = (bid & 63) * 1024 + it * 512 + tid;   // < 65536 per dir
        int lyr = local >> 15;
        int rem = local & 32767;
        int b = rem >> 9;
        int n = rem & 511;
        float v = lyr ? __ldcg(&g_h1f[0][dir][b * H + n]) : __ldcg(&g_h0f[0][dir][b * H + n]);
        out[(size_t)B * S * 2 * H + ((size_t)lyr * B + b) * (2 * H) + dir * H + n] = v;
    }
}

// ---------------- launch ----------------
extern "C" void kernel_launch(void* const* d_in, const int* in_sizes, int n_in,
                              void* d_out, int out_size) {
    const float* input  = (const float*)d_in[0];
    const float* enc    = (const float*)d_in[1];
    const float* Wih_f  = (const float*)d_in[2];
    const float* Whh_f  = (const float*)d_in[3];
    const float* bih_f  = (const float*)d_in[4];
    const float* bhh_f  = (const float*)d_in[5];
    const float* Wih_b  = (const float*)d_in[6];
    const float* Whh_b  = (const float*)d_in[7];
    const float* bih_b  = (const float*)d_in[8];
    const float* bhh_b  = (const float*)d_in[9];
    float* out = (float*)d_out;

    const int SMEM_P = 178176;
    static int configured = 0;
    if (!configured) {
        cudaFuncSetAttribute(gru_persist, cudaFuncAttributeMaxDynamicSharedMemorySize, SMEM_P);
        configured = 1;
    }

    conv_xw<<<17920, 256>>>(input, Wih_f, Wih_b);
    init_h<<<512, 256>>>(enc);
    gemm_gi0<<<dim3(S, 24, 2), 256>>>(bih_f, bih_b);
    gru_persist<<<NBLK, 512, SMEM_P>>>(Wih_f, Wih_b, Whh_f, Whh_b,
                                       bih_f, bih_b, bhh_f, bhh_b, out);
}